// round 1
// baseline (speedup 1.0000x reference)
#include <cuda_runtime.h>

// Problem constants
#define B_DIM 4
#define T_DIM 4096
#define E_DIM 2048
#define H_DIM 16
#define D_DIM 128
#define BT_DIM (B_DIM * T_DIM)   // 16384

// Scratch (device globals: no allocations allowed)
__device__ float g_Q[(size_t)BT_DIM * E_DIM];
__device__ float g_K[(size_t)BT_DIM * E_DIM];
__device__ float g_V[(size_t)BT_DIM * E_DIM];
__device__ float g_ATT[(size_t)BT_DIM * E_DIM];
__device__ float g_KV[B_DIM * H_DIM * D_DIM * D_DIM];

// Tiling
constexpr int BM = 128;
constexpr int BN = 128;
constexpr int BK = 16;

// ---------------------------------------------------------------------------
// C[M,N] = A[M,K] @ B[N,K]^T + bias[N]        (torch nn.Linear forward)
// M,N,K all multiples of 128/16; no bounds checks needed.
// ---------------------------------------------------------------------------
__global__ __launch_bounds__(256, 2)
void sgemm_nt(const float* __restrict__ A, const float* __restrict__ Bw,
              const float* __restrict__ bias, float* __restrict__ C,
              int M, int N, int K)
{
    __shared__ float As[BK][BM + 4];
    __shared__ float Bs[BK][BN + 4];

    const int tid = threadIdx.x;
    const int m0 = blockIdx.y * BM;
    const int n0 = blockIdx.x * BN;
    const int lr = tid >> 2;          // 0..63
    const int lc = (tid & 3) << 2;    // 0,4,8,12
    const int ty = tid >> 4;          // 0..15
    const int tx = tid & 15;          // 0..15

    float acc[8][8];
    #pragma unroll
    for (int i = 0; i < 8; i++)
        #pragma unroll
        for (int j = 0; j < 8; j++)
            acc[i][j] = 0.0f;

    const float* Ag = A + (size_t)m0 * K;
    const float* Bg = Bw + (size_t)n0 * K;

    for (int k0 = 0; k0 < K; k0 += BK) {
        #pragma unroll
        for (int r = 0; r < 2; r++) {
            int row = lr + r * 64;
            float4 va = *reinterpret_cast<const float4*>(Ag + (size_t)row * K + k0 + lc);
            As[lc + 0][row] = va.x; As[lc + 1][row] = va.y;
            As[lc + 2][row] = va.z; As[lc + 3][row] = va.w;
            float4 vb = *reinterpret_cast<const float4*>(Bg + (size_t)row * K + k0 + lc);
            Bs[lc + 0][row] = vb.x; Bs[lc + 1][row] = vb.y;
            Bs[lc + 2][row] = vb.z; Bs[lc + 3][row] = vb.w;
        }
        __syncthreads();

        #pragma unroll
        for (int k = 0; k < BK; k++) {
            float a[8], b[8];
            *reinterpret_cast<float4*>(a)     = *reinterpret_cast<const float4*>(&As[k][ty * 8]);
            *reinterpret_cast<float4*>(a + 4) = *reinterpret_cast<const float4*>(&As[k][ty * 8 + 4]);
            *reinterpret_cast<float4*>(b)     = *reinterpret_cast<const float4*>(&Bs[k][tx * 8]);
            *reinterpret_cast<float4*>(b + 4) = *reinterpret_cast<const float4*>(&Bs[k][tx * 8 + 4]);
            #pragma unroll
            for (int i = 0; i < 8; i++)
                #pragma unroll
                for (int j = 0; j < 8; j++)
                    acc[i][j] += a[i] * b[j];
        }
        __syncthreads();
    }

    #pragma unroll
    for (int i = 0; i < 8; i++) {
        int m = m0 + ty * 8 + i;
        float* Cr = C + (size_t)m * N + n0 + tx * 8;
        #pragma unroll
        for (int j = 0; j < 8; j += 4) {
            float4 v;
            v.x = acc[i][j + 0] + bias[n0 + tx * 8 + j + 0];
            v.y = acc[i][j + 1] + bias[n0 + tx * 8 + j + 1];
            v.z = acc[i][j + 2] + bias[n0 + tx * 8 + j + 2];
            v.w = acc[i][j + 3] + bias[n0 + tx * 8 + j + 3];
            *reinterpret_cast<float4*>(Cr + j) = v;
        }
    }
}

// ---------------------------------------------------------------------------
// KV[bh, d, e] = sum_s K[b, s, h, d] * V[b, s, h, e]     (A^T @ B per head)
// One CTA per (b,h): full 128x128 output, reduction over T=4096.
// ---------------------------------------------------------------------------
__global__ __launch_bounds__(256, 2)
void kv_kernel()
{
    const int bh = blockIdx.z;
    const int b = bh >> 4;
    const int h = bh & 15;
    const float* A  = g_K + (size_t)b * T_DIM * E_DIM + h * D_DIM;
    const float* Bv = g_V + (size_t)b * T_DIM * E_DIM + h * D_DIM;
    float* Cg = g_KV + bh * D_DIM * D_DIM;

    __shared__ float As[16][D_DIM];
    __shared__ float Bs[16][D_DIM];

    const int tid = threadIdx.x;
    const int lr = tid >> 5;          // 0..7
    const int lc = (tid & 31) << 2;   // 0..124
    const int ty = tid >> 4;
    const int tx = tid & 15;

    float acc[8][8];
    #pragma unroll
    for (int i = 0; i < 8; i++)
        #pragma unroll
        for (int j = 0; j < 8; j++)
            acc[i][j] = 0.0f;

    for (int s0 = 0; s0 < T_DIM; s0 += 16) {
        #pragma unroll
        for (int r = 0; r < 2; r++) {
            int s = lr + r * 8;
            *reinterpret_cast<float4*>(&As[s][lc]) =
                *reinterpret_cast<const float4*>(A + (size_t)(s0 + s) * E_DIM + lc);
            *reinterpret_cast<float4*>(&Bs[s][lc]) =
                *reinterpret_cast<const float4*>(Bv + (size_t)(s0 + s) * E_DIM + lc);
        }
        __syncthreads();

        #pragma unroll
        for (int k = 0; k < 16; k++) {
            float a[8], bb[8];
            *reinterpret_cast<float4*>(a)      = *reinterpret_cast<const float4*>(&As[k][ty * 8]);
            *reinterpret_cast<float4*>(a + 4)  = *reinterpret_cast<const float4*>(&As[k][ty * 8 + 4]);
            *reinterpret_cast<float4*>(bb)     = *reinterpret_cast<const float4*>(&Bs[k][tx * 8]);
            *reinterpret_cast<float4*>(bb + 4) = *reinterpret_cast<const float4*>(&Bs[k][tx * 8 + 4]);
            #pragma unroll
            for (int i = 0; i < 8; i++)
                #pragma unroll
                for (int j = 0; j < 8; j++)
                    acc[i][j] += a[i] * bb[j];
        }
        __syncthreads();
    }

    #pragma unroll
    for (int i = 0; i < 8; i++) {
        float* Cr = Cg + (ty * 8 + i) * D_DIM + tx * 8;
        #pragma unroll
        for (int j = 0; j < 8; j += 4) {
            float4 v;
            v.x = acc[i][j + 0]; v.y = acc[i][j + 1];
            v.z = acc[i][j + 2]; v.w = acc[i][j + 3];
            *reinterpret_cast<float4*>(Cr + j) = v;
        }
    }
}

// ---------------------------------------------------------------------------
// ATT[b, t, h, :] = scale * Q[b, t, h, :] @ KV[bh]      ([T,128] @ [128,128])
// grid: (1, T/128, B*H)
// ---------------------------------------------------------------------------
__global__ __launch_bounds__(256, 2)
void attn_kernel()
{
    const float scale = 0.088388347648318447f;  // 1/sqrt(128)
    const int bh = blockIdx.z;
    const int b = bh >> 4;
    const int h = bh & 15;
    const int m0 = blockIdx.y * BM;

    const float* A  = g_Q + (size_t)b * T_DIM * E_DIM + h * D_DIM;   // [T,128] ld=E
    const float* Bk = g_KV + bh * D_DIM * D_DIM;                      // [128,128]
    float* Cg = g_ATT + (size_t)b * T_DIM * E_DIM + h * D_DIM;

    __shared__ float As[BK][BM + 4];
    __shared__ float Bs[BK][D_DIM];

    const int tid = threadIdx.x;
    const int lr = tid >> 2;          // 0..63  (A tile)
    const int lc = (tid & 3) << 2;    // 0,4,8,12
    const int br = tid >> 5;          // 0..7   (B tile)
    const int bc = (tid & 31) << 2;   // 0..124
    const int ty = tid >> 4;
    const int tx = tid & 15;

    float acc[8][8];
    #pragma unroll
    for (int i = 0; i < 8; i++)
        #pragma unroll
        for (int j = 0; j < 8; j++)
            acc[i][j] = 0.0f;

    for (int k0 = 0; k0 < D_DIM; k0 += BK) {
        #pragma unroll
        for (int r = 0; r < 2; r++) {
            int row = lr + r * 64;
            float4 va = *reinterpret_cast<const float4*>(A + (size_t)(m0 + row) * E_DIM + k0 + lc);
            As[lc + 0][row] = va.x; As[lc + 1][row] = va.y;
            As[lc + 2][row] = va.z; As[lc + 3][row] = va.w;
            int s = br + r * 8;
            *reinterpret_cast<float4*>(&Bs[s][bc]) =
                *reinterpret_cast<const float4*>(Bk + (k0 + s) * D_DIM + bc);
        }
        __syncthreads();

        #pragma unroll
        for (int k = 0; k < BK; k++) {
            float a[8], bb[8];
            *reinterpret_cast<float4*>(a)      = *reinterpret_cast<const float4*>(&As[k][ty * 8]);
            *reinterpret_cast<float4*>(a + 4)  = *reinterpret_cast<const float4*>(&As[k][ty * 8 + 4]);
            *reinterpret_cast<float4*>(bb)     = *reinterpret_cast<const float4*>(&Bs[k][tx * 8]);
            *reinterpret_cast<float4*>(bb + 4) = *reinterpret_cast<const float4*>(&Bs[k][tx * 8 + 4]);
            #pragma unroll
            for (int i = 0; i < 8; i++)
                #pragma unroll
                for (int j = 0; j < 8; j++)
                    acc[i][j] += a[i] * bb[j];
        }
        __syncthreads();
    }

    #pragma unroll
    for (int i = 0; i < 8; i++) {
        float* Cr = Cg + (size_t)(m0 + ty * 8 + i) * E_DIM + tx * 8;
        #pragma unroll
        for (int j = 0; j < 8; j += 4) {
            float4 v;
            v.x = acc[i][j + 0] * scale; v.y = acc[i][j + 1] * scale;
            v.z = acc[i][j + 2] * scale; v.w = acc[i][j + 3] * scale;
            *reinterpret_cast<float4*>(Cr + j) = v;
        }
    }
}

// ---------------------------------------------------------------------------
extern "C" void kernel_launch(void* const* d_in, const int* in_sizes, int n_in,
                              void* d_out, int out_size)
{
    const float* x  = (const float*)d_in[0];
    const float* Wq = (const float*)d_in[1];
    const float* bq = (const float*)d_in[2];
    const float* Wk = (const float*)d_in[3];
    const float* bk = (const float*)d_in[4];
    const float* Wv = (const float*)d_in[5];
    const float* bv = (const float*)d_in[6];
    const float* Wo = (const float*)d_in[7];
    const float* bo = (const float*)d_in[8];
    float* out = (float*)d_out;

    float *Q, *K, *V, *ATT;
    cudaGetSymbolAddress((void**)&Q,   g_Q);
    cudaGetSymbolAddress((void**)&K,   g_K);
    cudaGetSymbolAddress((void**)&V,   g_V);
    cudaGetSymbolAddress((void**)&ATT, g_ATT);

    dim3 blk(256);
    dim3 grid_proj(E_DIM / BN, BT_DIM / BM);   // (16, 128)

    sgemm_nt<<<grid_proj, blk>>>(x, Wq, bq, Q, BT_DIM, E_DIM, E_DIM);
    sgemm_nt<<<grid_proj, blk>>>(x, Wk, bk, K, BT_DIM, E_DIM, E_DIM);
    sgemm_nt<<<grid_proj, blk>>>(x, Wv, bv, V, BT_DIM, E_DIM, E_DIM);

    kv_kernel<<<dim3(1, 1, B_DIM * H_DIM), blk>>>();

    attn_kernel<<<dim3(1, T_DIM / BM, B_DIM * H_DIM), blk>>>();

    sgemm_nt<<<grid_proj, blk>>>(ATT, Wo, bo, out, BT_DIM, E_DIM, E_DIM);
}

// round 3
// speedup vs baseline: 3.1965x; 3.1965x over previous
#include <cuda_runtime.h>
#include <cuda_bf16.h>
#include <cstdint>

#define B_DIM 4
#define T_DIM 4096
#define E_DIM 2048
#define H_DIM 16
#define D_DIM 128
#define BT_DIM 16384
#define KVSPLIT 8

typedef __nv_bfloat16 bf16;

// ---------------- scratch (device globals; no allocations allowed) ----------
__device__ bf16 g_xhi[(size_t)BT_DIM * E_DIM];
__device__ bf16 g_xlo[(size_t)BT_DIM * E_DIM];
__device__ bf16 g_Whi[4][(size_t)E_DIM * E_DIM];
__device__ bf16 g_Wlo[4][(size_t)E_DIM * E_DIM];
__device__ bf16 g_Qhi[(size_t)BT_DIM * E_DIM];
__device__ bf16 g_Qlo[(size_t)BT_DIM * E_DIM];
__device__ float g_K[(size_t)BT_DIM * E_DIM];
__device__ float g_V[(size_t)BT_DIM * E_DIM];
__device__ bf16 g_AThi[(size_t)BT_DIM * E_DIM];
__device__ bf16 g_ATlo[(size_t)BT_DIM * E_DIM];
__device__ float g_KVp[(size_t)KVSPLIT * 64 * D_DIM * D_DIM];
__device__ bf16 g_KVthi[64 * D_DIM * D_DIM];
__device__ bf16 g_KVtlo[64 * D_DIM * D_DIM];

// ---------------- helpers ----------------------------------------------------
__device__ __forceinline__ uint32_t smem_u32(const void* p) {
    uint32_t a;
    asm("{ .reg .u64 t; cvta.to.shared.u64 t, %1; cvt.u32.u64 %0, t; }" : "=r"(a) : "l"(p));
    return a;
}

__device__ __forceinline__ void cp_async16(uint32_t sdst, const void* gsrc) {
    asm volatile("cp.async.cg.shared.global [%0], [%1], 16;" :: "r"(sdst), "l"(gsrc) : "memory");
}
#define CP_COMMIT() asm volatile("cp.async.commit_group;" ::: "memory")
#define CP_WAIT2()  asm volatile("cp.async.wait_group 2;" ::: "memory")

__device__ __forceinline__ void ldsm4(uint32_t* r, uint32_t a) {
    asm volatile("ldmatrix.sync.aligned.m8n8.x4.shared.b16 {%0,%1,%2,%3}, [%4];"
                 : "=r"(r[0]), "=r"(r[1]), "=r"(r[2]), "=r"(r[3]) : "r"(a));
}

__device__ __forceinline__ void mma16816(float* c, const uint32_t* a, const uint32_t* b) {
    asm volatile(
        "mma.sync.aligned.m16n8k16.row.col.f32.bf16.bf16.f32 "
        "{%0,%1,%2,%3}, {%4,%5,%6,%7}, {%8,%9}, {%0,%1,%2,%3};"
        : "+f"(c[0]), "+f"(c[1]), "+f"(c[2]), "+f"(c[3])
        : "r"(a[0]), "r"(a[1]), "r"(a[2]), "r"(a[3]), "r"(b[0]), "r"(b[1]));
}

// ---------------- tensor-core GEMM core --------------------------------------
// C[128,128] tile of alpha*(A @ B^T) + bias, A/B bf16 hi/lo pairs, K-major.
// Smem tile layout: 128 rows x 32 cols bf16 (64B/row, 4 16B-chunks),
// chunk swizzle c' = c ^ ((row>>1)&3)  -> conflict-free ldmatrix + stores.
#define STAGE_BYTES 32768
#define SMEM_BYTES  (3 * STAGE_BYTES)

__device__ __forceinline__ void load_tile(uint32_t sdst, const bf16* __restrict__ g,
                                          int row0, int col0, int ld) {
    const int t = threadIdx.x;
    #pragma unroll
    for (int i = 0; i < 2; i++) {
        int idx = t + i * 256;             // 0..511
        int r = idx >> 2, c = idx & 3;
        const bf16* src = g + (size_t)(row0 + r) * ld + col0 + c * 8;
        uint32_t off = r * 64 + ((c ^ ((r >> 1) & 3)) << 4);
        cp_async16(sdst + off, src);
    }
}

// OUT_MODE 0: fp32 to Cf.   OUT_MODE 1: hi/lo bf16 to Chi/Clo.
template <int OUT_MODE>
__device__ __forceinline__ void gemm_core(
    const bf16* __restrict__ Ahi, const bf16* __restrict__ Alo,
    int row0, int acol, int lda,
    const bf16* __restrict__ Bhi, const bf16* __restrict__ Blo,
    int n0, int ldb, int K,
    float alpha, const float* __restrict__ bias,
    float* __restrict__ Cf, bf16* __restrict__ Chi, bf16* __restrict__ Clo,
    int c_row0, int c_col0, int ldc)
{
    extern __shared__ __align__(1024) char smdyn[];
    const uint32_t sbase = smem_u32(smdyn);
    const int tid = threadIdx.x;
    const int wid = tid >> 5, lane = tid & 31;
    const int wm = (wid & 1) * 64;      // warp m-offset (2 warps over 128)
    const int wn = (wid >> 1) * 32;     // warp n-offset (4 warps over 128)
    const int NC = K >> 5;              // chunks of BK=32

    // Precompute lane-dependent smem offsets for ldmatrix.
    // A: lanes 0-15 rows m..m+15 @kchunk0, 16-31 same rows @kchunk1 (x4 order = a0..a3)
    uint32_t aoff[4][2];
    #pragma unroll
    for (int mi = 0; mi < 4; mi++) {
        int r = wm + mi * 16 + (lane & 15);
        #pragma unroll
        for (int ks = 0; ks < 2; ks++) {
            int kc = ks * 2 + (lane >> 4);
            aoff[mi][ks] = r * 64 + ((kc ^ ((r >> 1) & 3)) << 4);
        }
    }
    // B: group=lane>>3: rows n..n+7 (groups 0,1) then n+8..n+15 (groups 2,3),
    // kchunk alternates within group pairs -> x4 gives b(n),b(n+8) frags.
    uint32_t boff[2][2];
    #pragma unroll
    for (int p = 0; p < 2; p++) {
        int g2 = lane >> 3;
        int r = wn + p * 16 + ((g2 >> 1) << 3) + (lane & 7);
        #pragma unroll
        for (int ks = 0; ks < 2; ks++) {
            int kc = ks * 2 + (g2 & 1);
            boff[p][ks] = r * 64 + ((kc ^ ((r >> 1) & 3)) << 4);
        }
    }

    float acc[4][4][4];
    #pragma unroll
    for (int mi = 0; mi < 4; mi++)
        #pragma unroll
        for (int ni = 0; ni < 4; ni++)
            #pragma unroll
            for (int q = 0; q < 4; q++) acc[mi][ni][q] = 0.0f;

    // prologue: stages 0,1
    #pragma unroll
    for (int i = 0; i < 2; i++) {
        if (i < NC) {
            uint32_t sb = sbase + i * STAGE_BYTES;
            int k0 = i * 32;
            load_tile(sb + 0,     Ahi, row0, acol + k0, lda);
            load_tile(sb + 8192,  Alo, row0, acol + k0, lda);
            load_tile(sb + 16384, Bhi, n0, k0, ldb);
            load_tile(sb + 24576, Blo, n0, k0, ldb);
        }
        CP_COMMIT();
    }

    for (int c = 0; c < NC; c++) {
        // issue load for stage c+2
        if (c + 2 < NC) {
            uint32_t sb = sbase + ((c + 2) % 3) * STAGE_BYTES;
            int k0 = (c + 2) * 32;
            load_tile(sb + 0,     Ahi, row0, acol + k0, lda);
            load_tile(sb + 8192,  Alo, row0, acol + k0, lda);
            load_tile(sb + 16384, Bhi, n0, k0, ldb);
            load_tile(sb + 24576, Blo, n0, k0, ldb);
        }
        CP_COMMIT();
        CP_WAIT2();          // stage c resident
        __syncthreads();

        const uint32_t sb = sbase + (c % 3) * STAGE_BYTES;
        #pragma unroll
        for (int ks = 0; ks < 2; ks++) {
            uint32_t ah[4][4], al[4][4], bh[4][2], bl[4][2];
            #pragma unroll
            for (int mi = 0; mi < 4; mi++) {
                ldsm4(ah[mi], sb + aoff[mi][ks]);
                ldsm4(al[mi], sb + 8192 + aoff[mi][ks]);
            }
            #pragma unroll
            for (int p = 0; p < 2; p++) {
                uint32_t t4[4];
                ldsm4(t4, sb + 16384 + boff[p][ks]);
                bh[2 * p][0] = t4[0]; bh[2 * p][1] = t4[1];
                bh[2 * p + 1][0] = t4[2]; bh[2 * p + 1][1] = t4[3];
                ldsm4(t4, sb + 24576 + boff[p][ks]);
                bl[2 * p][0] = t4[0]; bl[2 * p][1] = t4[1];
                bl[2 * p + 1][0] = t4[2]; bl[2 * p + 1][1] = t4[3];
            }
            #pragma unroll
            for (int mi = 0; mi < 4; mi++)
                #pragma unroll
                for (int ni = 0; ni < 4; ni++) {
                    mma16816(acc[mi][ni], ah[mi], bh[ni]);
                    mma16816(acc[mi][ni], ah[mi], bl[ni]);
                    mma16816(acc[mi][ni], al[mi], bh[ni]);
                }
        }
        __syncthreads();     // protect stage before rewrite
    }

    // ---- epilogue ----
    const int lg = lane >> 2;            // row group 0..7
    const int lc2 = (lane & 3) * 2;      // col pair
    #pragma unroll
    for (int mi = 0; mi < 4; mi++) {
        #pragma unroll
        for (int half = 0; half < 2; half++) {
            int row = c_row0 + wm + mi * 16 + lg + half * 8;
            #pragma unroll
            for (int ni = 0; ni < 4; ni++) {
                int col = c_col0 + n0 + wn + ni * 8 + lc2;
                float v0 = alpha * acc[mi][ni][half * 2 + 0];
                float v1 = alpha * acc[mi][ni][half * 2 + 1];
                if (bias) { v0 += bias[col]; v1 += bias[col + 1]; }
                if (OUT_MODE == 0) {
                    *reinterpret_cast<float2*>(Cf + (size_t)row * ldc + col) = make_float2(v0, v1);
                } else {
                    bf16 h0 = __float2bfloat16(v0);
                    bf16 h1 = __float2bfloat16(v1);
                    bf16 l0 = __float2bfloat16(v0 - __bfloat162float(h0));
                    bf16 l1 = __float2bfloat16(v1 - __bfloat162float(h1));
                    uint32_t hw = (uint32_t)__bfloat16_as_ushort(h0) | ((uint32_t)__bfloat16_as_ushort(h1) << 16);
                    uint32_t lw = (uint32_t)__bfloat16_as_ushort(l0) | ((uint32_t)__bfloat16_as_ushort(l1) << 16);
                    *reinterpret_cast<uint32_t*>(Chi + (size_t)row * ldc + col) = hw;
                    *reinterpret_cast<uint32_t*>(Clo + (size_t)row * ldc + col) = lw;
                }
            }
        }
    }
}

// ---------------- kernels ----------------------------------------------------
template <int OUT_MODE>
__global__ __launch_bounds__(256) void k_gemm_proj(
    const bf16* Ahi, const bf16* Alo, const bf16* Bhi, const bf16* Blo,
    const float* bias, float* Cf, bf16* Chi, bf16* Clo)
{
    gemm_core<OUT_MODE>(Ahi, Alo, blockIdx.y * 128, 0, E_DIM,
                        Bhi, Blo, blockIdx.x * 128, E_DIM, E_DIM,
                        1.0f, bias, Cf, Chi, Clo,
                        blockIdx.y * 128, 0, E_DIM);
}

__global__ __launch_bounds__(256) void k_gemm_attn()
{
    const int h = blockIdx.z;
    const int row0 = blockIdx.y * 128;
    const int b = row0 >> 12;
    const int bh = (b << 4) + h;
    gemm_core<1>(g_Qhi, g_Qlo, row0, h * 128, E_DIM,
                 g_KVthi + ((size_t)bh << 14), g_KVtlo + ((size_t)bh << 14), 0, D_DIM, D_DIM,
                 0.08838834764831845f, nullptr, nullptr, g_AThi, g_ATlo,
                 row0, h * 128, E_DIM);
}

// fp32 -> bf16 hi/lo split
__global__ __launch_bounds__(256) void k_split(const float* __restrict__ in,
                                               bf16* __restrict__ hi, bf16* __restrict__ lo, int n)
{
    int i = (blockIdx.x * 256 + threadIdx.x) * 4;
    if (i >= n) return;
    float4 v = *reinterpret_cast<const float4*>(in + i);
    float vv[4] = {v.x, v.y, v.z, v.w};
    uint32_t hw[2], lw[2];
    #pragma unroll
    for (int q = 0; q < 2; q++) {
        bf16 h0 = __float2bfloat16(vv[q * 2 + 0]);
        bf16 h1 = __float2bfloat16(vv[q * 2 + 1]);
        bf16 l0 = __float2bfloat16(vv[q * 2 + 0] - __bfloat162float(h0));
        bf16 l1 = __float2bfloat16(vv[q * 2 + 1] - __bfloat162float(h1));
        hw[q] = (uint32_t)__bfloat16_as_ushort(h0) | ((uint32_t)__bfloat16_as_ushort(h1) << 16);
        lw[q] = (uint32_t)__bfloat16_as_ushort(l0) | ((uint32_t)__bfloat16_as_ushort(l1) << 16);
    }
    *reinterpret_cast<uint2*>(hi + i) = make_uint2(hw[0], hw[1]);
    *reinterpret_cast<uint2*>(lo + i) = make_uint2(lw[0], lw[1]);
}

// KVt partial: KVt[bh][e][d] = sum_{s in split} V[b,s,h,e] * K[b,s,h,d]
__global__ __launch_bounds__(256, 2) void k_kvpart()
{
    const int split = blockIdx.x;
    const int bh = blockIdx.z;
    const int b = bh >> 4;
    const int h = bh & 15;
    const float* A  = g_V + (size_t)b * T_DIM * E_DIM + h * D_DIM;
    const float* Bk = g_K + (size_t)b * T_DIM * E_DIM + h * D_DIM;
    float* Cg = g_KVp + ((size_t)(split * 64 + bh) << 14);

    __shared__ float As[16][D_DIM];
    __shared__ float Bs[16][D_DIM];

    const int tid = threadIdx.x;
    const int lr = tid >> 5;
    const int lc = (tid & 31) << 2;
    const int ty = tid >> 4;
    const int tx = tid & 15;

    float acc[8][8];
    #pragma unroll
    for (int i = 0; i < 8; i++)
        #pragma unroll
        for (int j = 0; j < 8; j++) acc[i][j] = 0.0f;

    const int s_begin = split * (T_DIM / KVSPLIT);
    const int s_end = s_begin + (T_DIM / KVSPLIT);
    for (int s0 = s_begin; s0 < s_end; s0 += 16) {
        #pragma unroll
        for (int rr = 0; rr < 2; rr++) {
            int s = lr + rr * 8;
            *reinterpret_cast<float4*>(&As[s][lc]) =
                *reinterpret_cast<const float4*>(A + (size_t)(s0 + s) * E_DIM + lc);
            *reinterpret_cast<float4*>(&Bs[s][lc]) =
                *reinterpret_cast<const float4*>(Bk + (size_t)(s0 + s) * E_DIM + lc);
        }
        __syncthreads();
        #pragma unroll
        for (int k = 0; k < 16; k++) {
            float a[8], bb[8];
            *reinterpret_cast<float4*>(a)      = *reinterpret_cast<const float4*>(&As[k][ty * 8]);
            *reinterpret_cast<float4*>(a + 4)  = *reinterpret_cast<const float4*>(&As[k][ty * 8 + 4]);
            *reinterpret_cast<float4*>(bb)     = *reinterpret_cast<const float4*>(&Bs[k][tx * 8]);
            *reinterpret_cast<float4*>(bb + 4) = *reinterpret_cast<const float4*>(&Bs[k][tx * 8 + 4]);
            #pragma unroll
            for (int i = 0; i < 8; i++)
                #pragma unroll
                for (int j = 0; j < 8; j++) acc[i][j] += a[i] * bb[j];
        }
        __syncthreads();
    }

    #pragma unroll
    for (int i = 0; i < 8; i++) {
        float* Cr = Cg + (ty * 8 + i) * D_DIM + tx * 8;
        #pragma unroll
        for (int j = 0; j < 8; j += 4)
            *reinterpret_cast<float4*>(Cr + j) = make_float4(acc[i][j], acc[i][j + 1], acc[i][j + 2], acc[i][j + 3]);
    }
}

// reduce 8 partials -> bf16 hi/lo
__global__ __launch_bounds__(256) void k_kvreduce()
{
    int idx = blockIdx.x * 256 + threadIdx.x;
    float s = 0.0f;
    #pragma unroll
    for (int p = 0; p < KVSPLIT; p++) s += g_KVp[((size_t)p << 20) + idx];
    bf16 h = __float2bfloat16(s);
    g_KVthi[idx] = h;
    g_KVtlo[idx] = __float2bfloat16(s - __bfloat162float(h));
}

// ---------------- launch -----------------------------------------------------
extern "C" void kernel_launch(void* const* d_in, const int* in_sizes, int n_in,
                              void* d_out, int out_size)
{
    const float* x  = (const float*)d_in[0];
    const float* Wq = (const float*)d_in[1];
    const float* bq = (const float*)d_in[2];
    const float* Wk = (const float*)d_in[3];
    const float* bk = (const float*)d_in[4];
    const float* Wv = (const float*)d_in[5];
    const float* bv = (const float*)d_in[6];
    const float* Wo = (const float*)d_in[7];
    const float* bo = (const float*)d_in[8];
    float* out = (float*)d_out;

    bf16 *xhi, *xlo, *whi, *wlo, *qhi, *qlo, *athi, *atlo;
    float *Kf, *Vf;
    cudaGetSymbolAddress((void**)&xhi, g_xhi);
    cudaGetSymbolAddress((void**)&xlo, g_xlo);
    cudaGetSymbolAddress((void**)&whi, g_Whi);
    cudaGetSymbolAddress((void**)&wlo, g_Wlo);
    cudaGetSymbolAddress((void**)&qhi, g_Qhi);
    cudaGetSymbolAddress((void**)&qlo, g_Qlo);
    cudaGetSymbolAddress((void**)&Kf,  g_K);
    cudaGetSymbolAddress((void**)&Vf,  g_V);
    cudaGetSymbolAddress((void**)&athi, g_AThi);
    cudaGetSymbolAddress((void**)&atlo, g_ATlo);

    cudaFuncSetAttribute(k_gemm_proj<0>, cudaFuncAttributeMaxDynamicSharedMemorySize, SMEM_BYTES);
    cudaFuncSetAttribute(k_gemm_proj<1>, cudaFuncAttributeMaxDynamicSharedMemorySize, SMEM_BYTES);
    cudaFuncSetAttribute(k_gemm_attn,    cudaFuncAttributeMaxDynamicSharedMemorySize, SMEM_BYTES);

    const size_t WSZ = (size_t)E_DIM * E_DIM;
    const int NX = BT_DIM * E_DIM;

    k_split<<<NX / 1024, 256>>>(x, xhi, xlo, NX);
    k_split<<<(int)(WSZ / 1024), 256>>>(Wq, whi + 0 * WSZ, wlo + 0 * WSZ, (int)WSZ);
    k_split<<<(int)(WSZ / 1024), 256>>>(Wk, whi + 1 * WSZ, wlo + 1 * WSZ, (int)WSZ);
    k_split<<<(int)(WSZ / 1024), 256>>>(Wv, whi + 2 * WSZ, wlo + 2 * WSZ, (int)WSZ);
    k_split<<<(int)(WSZ / 1024), 256>>>(Wo, whi + 3 * WSZ, wlo + 3 * WSZ, (int)WSZ);

    dim3 gp(E_DIM / 128, BT_DIM / 128);  // (16, 128)

    k_gemm_proj<1><<<gp, 256, SMEM_BYTES>>>(xhi, xlo, whi + 0 * WSZ, wlo + 0 * WSZ, bq, nullptr, qhi, qlo);
    k_gemm_proj<0><<<gp, 256, SMEM_BYTES>>>(xhi, xlo, whi + 1 * WSZ, wlo + 1 * WSZ, bk, Kf, nullptr, nullptr);
    k_gemm_proj<0><<<gp, 256, SMEM_BYTES>>>(xhi, xlo, whi + 2 * WSZ, wlo + 2 * WSZ, bv, Vf, nullptr, nullptr);

    k_kvpart<<<dim3(KVSPLIT, 1, 64), 256>>>();
    k_kvreduce<<<(64 * D_DIM * D_DIM) / 256, 256>>>();

    k_gemm_attn<<<dim3(1, BT_DIM / 128, H_DIM), 256, SMEM_BYTES>>>();

    k_gemm_proj<0><<<gp, 256, SMEM_BYTES>>>(athi, atlo, whi + 3 * WSZ, wlo + 3 * WSZ, bo, out, nullptr, nullptr);
}

// round 4
// speedup vs baseline: 3.2088x; 1.0038x over previous
#include <cuda_runtime.h>
#include <cuda_fp16.h>
#include <cstdint>

#define B_DIM 4
#define T_DIM 4096
#define E_DIM 2048
#define H_DIM 16
#define D_DIM 128
#define BT_DIM 16384
#define KVSPLIT 8

typedef __half f16;

// ---------------- scratch (device globals; no allocations allowed) ----------
// "h" plane = fp16(v), "c" plane = fp16(hi + 32*(v-hi))  (compensation operand)
__device__ f16 g_xh[(size_t)BT_DIM * E_DIM];
__device__ f16 g_xc[(size_t)BT_DIM * E_DIM];
__device__ f16 g_Wh[4][(size_t)E_DIM * E_DIM];
__device__ f16 g_Wc[4][(size_t)E_DIM * E_DIM];
__device__ f16 g_Qh[(size_t)BT_DIM * E_DIM];
__device__ f16 g_Qc[(size_t)BT_DIM * E_DIM];
__device__ float g_K[(size_t)BT_DIM * E_DIM];
__device__ float g_V[(size_t)BT_DIM * E_DIM];
__device__ f16 g_ATh[(size_t)BT_DIM * E_DIM];
__device__ f16 g_ATc[(size_t)BT_DIM * E_DIM];
__device__ float g_KVp[(size_t)KVSPLIT * 64 * D_DIM * D_DIM];
__device__ f16 g_KVth[64 * D_DIM * D_DIM];
__device__ f16 g_KVtc[64 * D_DIM * D_DIM];

#define SPLIT_S    32.0f
#define COMB_A     0.96875f    // 1 - 1/32
#define COMB_B     0.03125f    // 1/32

// ---------------- helpers ----------------------------------------------------
__device__ __forceinline__ uint32_t smem_u32(const void* p) {
    uint32_t a;
    asm("{ .reg .u64 t; cvta.to.shared.u64 t, %1; cvt.u32.u64 %0, t; }" : "=r"(a) : "l"(p));
    return a;
}

__device__ __forceinline__ void cp_async16(uint32_t sdst, const void* gsrc) {
    asm volatile("cp.async.cg.shared.global [%0], [%1], 16;" :: "r"(sdst), "l"(gsrc) : "memory");
}
#define CP_COMMIT() asm volatile("cp.async.commit_group;" ::: "memory")
#define CP_WAIT2()  asm volatile("cp.async.wait_group 2;" ::: "memory")

__device__ __forceinline__ void ldsm4(uint32_t* r, uint32_t a) {
    asm volatile("ldmatrix.sync.aligned.m8n8.x4.shared.b16 {%0,%1,%2,%3}, [%4];"
                 : "=r"(r[0]), "=r"(r[1]), "=r"(r[2]), "=r"(r[3]) : "r"(a));
}

__device__ __forceinline__ void mma16816(float* c, const uint32_t* a, const uint32_t* b) {
    asm volatile(
        "mma.sync.aligned.m16n8k16.row.col.f32.f16.f16.f32 "
        "{%0,%1,%2,%3}, {%4,%5,%6,%7}, {%8,%9}, {%0,%1,%2,%3};"
        : "+f"(c[0]), "+f"(c[1]), "+f"(c[2]), "+f"(c[3])
        : "r"(a[0]), "r"(a[1]), "r"(a[2]), "r"(a[3]), "r"(b[0]), "r"(b[1]));
}

// split v -> (h, c) fp16 pair
__device__ __forceinline__ void split2(float v, f16& h, f16& c) {
    h = __float2half_rn(v);
    float lo = v - __half2float(h);
    c = __float2half_rn(__half2float(h) + SPLIT_S * lo);
}

// ---------------- tensor-core GEMM core --------------------------------------
// C[128,128] tile of alpha*(A @ B^T) + bias via compensated 2-pass fp16.
// Smem tile: 128 rows x 32 cols fp16 (64B/row, 4 16B-chunks),
// chunk swizzle c' = c ^ ((row>>1)&3).
#define STAGE_BYTES 32768
#define SMEM_BYTES  (3 * STAGE_BYTES)

__device__ __forceinline__ void load_tile(uint32_t sdst, const f16* __restrict__ g,
                                          int row0, int col0, int ld) {
    const int t = threadIdx.x;
    #pragma unroll
    for (int i = 0; i < 2; i++) {
        int idx = t + i * 256;             // 0..511
        int r = idx >> 2, c = idx & 3;
        const f16* src = g + (size_t)(row0 + r) * ld + col0 + c * 8;
        uint32_t off = r * 64 + ((c ^ ((r >> 1) & 3)) << 4);
        cp_async16(sdst + off, src);
    }
}

// OUT_MODE 0: fp32 to Cf.   OUT_MODE 1: (h,c) fp16 pair to Chp/Ccp.
template <int OUT_MODE>
__device__ __forceinline__ void gemm_core(
    const f16* __restrict__ Ah, const f16* __restrict__ Ac,
    int row0, int acol, int lda,
    const f16* __restrict__ Bh, const f16* __restrict__ Bc,
    int n0, int ldb, int K,
    float alpha, const float* __restrict__ bias,
    float* __restrict__ Cf, f16* __restrict__ Chp, f16* __restrict__ Ccp,
    int c_row0, int c_col0, int ldc)
{
    extern __shared__ __align__(1024) char smdyn[];
    const uint32_t sbase = smem_u32(smdyn);
    const int tid = threadIdx.x;
    const int wid = tid >> 5, lane = tid & 31;
    const int wm = (wid & 1) * 64;
    const int wn = (wid >> 1) * 32;
    const int NC = K >> 5;

    uint32_t aoff[4][2];
    #pragma unroll
    for (int mi = 0; mi < 4; mi++) {
        int r = wm + mi * 16 + (lane & 15);
        #pragma unroll
        for (int ks = 0; ks < 2; ks++) {
            int kc = ks * 2 + (lane >> 4);
            aoff[mi][ks] = r * 64 + ((kc ^ ((r >> 1) & 3)) << 4);
        }
    }
    uint32_t boff[2][2];
    #pragma unroll
    for (int p = 0; p < 2; p++) {
        int g2 = lane >> 3;
        int r = wn + p * 16 + ((g2 >> 1) << 3) + (lane & 7);
        #pragma unroll
        for (int ks = 0; ks < 2; ks++) {
            int kc = ks * 2 + (g2 & 1);
            boff[p][ks] = r * 64 + ((kc ^ ((r >> 1) & 3)) << 4);
        }
    }

    float accA[4][4][4];
    float accB[4][4][4];
    #pragma unroll
    for (int mi = 0; mi < 4; mi++)
        #pragma unroll
        for (int ni = 0; ni < 4; ni++)
            #pragma unroll
            for (int q = 0; q < 4; q++) { accA[mi][ni][q] = 0.0f; accB[mi][ni][q] = 0.0f; }

    #pragma unroll
    for (int i = 0; i < 2; i++) {
        if (i < NC) {
            uint32_t sb = sbase + i * STAGE_BYTES;
            int k0 = i * 32;
            load_tile(sb + 0,     Ah, row0, acol + k0, lda);
            load_tile(sb + 8192,  Ac, row0, acol + k0, lda);
            load_tile(sb + 16384, Bh, n0, k0, ldb);
            load_tile(sb + 24576, Bc, n0, k0, ldb);
        }
        CP_COMMIT();
    }

    for (int c = 0; c < NC; c++) {
        if (c + 2 < NC) {
            uint32_t sb = sbase + ((c + 2) % 3) * STAGE_BYTES;
            int k0 = (c + 2) * 32;
            load_tile(sb + 0,     Ah, row0, acol + k0, lda);
            load_tile(sb + 8192,  Ac, row0, acol + k0, lda);
            load_tile(sb + 16384, Bh, n0, k0, ldb);
            load_tile(sb + 24576, Bc, n0, k0, ldb);
        }
        CP_COMMIT();
        CP_WAIT2();
        __syncthreads();

        const uint32_t sb = sbase + (c % 3) * STAGE_BYTES;
        #pragma unroll
        for (int ks = 0; ks < 2; ks++) {
            uint32_t ah[4][4], a2[4][4], bh[4][2], b2[4][2];
            #pragma unroll
            for (int mi = 0; mi < 4; mi++) {
                ldsm4(ah[mi], sb + aoff[mi][ks]);
                ldsm4(a2[mi], sb + 8192 + aoff[mi][ks]);
            }
            #pragma unroll
            for (int p = 0; p < 2; p++) {
                uint32_t t4[4];
                ldsm4(t4, sb + 16384 + boff[p][ks]);
                bh[2 * p][0] = t4[0]; bh[2 * p][1] = t4[1];
                bh[2 * p + 1][0] = t4[2]; bh[2 * p + 1][1] = t4[3];
                ldsm4(t4, sb + 24576 + boff[p][ks]);
                b2[2 * p][0] = t4[0]; b2[2 * p][1] = t4[1];
                b2[2 * p + 1][0] = t4[2]; b2[2 * p + 1][1] = t4[3];
            }
            #pragma unroll
            for (int mi = 0; mi < 4; mi++)
                #pragma unroll
                for (int ni = 0; ni < 4; ni++) {
                    mma16816(accA[mi][ni], ah[mi], bh[ni]);
                    mma16816(accB[mi][ni], a2[mi], b2[ni]);
                }
        }
        __syncthreads();
    }

    // ---- epilogue: v = alpha*(COMB_A*accA + COMB_B*accB) + bias ----
    const int lg = lane >> 2;
    const int lc2 = (lane & 3) * 2;
    #pragma unroll
    for (int mi = 0; mi < 4; mi++) {
        #pragma unroll
        for (int half = 0; half < 2; half++) {
            int row = c_row0 + wm + mi * 16 + lg + half * 8;
            #pragma unroll
            for (int ni = 0; ni < 4; ni++) {
                int col = c_col0 + n0 + wn + ni * 8 + lc2;
                float v0 = COMB_A * accA[mi][ni][half * 2 + 0] + COMB_B * accB[mi][ni][half * 2 + 0];
                float v1 = COMB_A * accA[mi][ni][half * 2 + 1] + COMB_B * accB[mi][ni][half * 2 + 1];
                v0 *= alpha; v1 *= alpha;
                if (bias) { v0 += bias[col]; v1 += bias[col + 1]; }
                if (OUT_MODE == 0) {
                    *reinterpret_cast<float2*>(Cf + (size_t)row * ldc + col) = make_float2(v0, v1);
                } else {
                    f16 h0, c0, h1, c1;
                    split2(v0, h0, c0);
                    split2(v1, h1, c1);
                    uint32_t hw = (uint32_t)__half_as_ushort(h0) | ((uint32_t)__half_as_ushort(h1) << 16);
                    uint32_t cw = (uint32_t)__half_as_ushort(c0) | ((uint32_t)__half_as_ushort(c1) << 16);
                    *reinterpret_cast<uint32_t*>(Chp + (size_t)row * ldc + col) = hw;
                    *reinterpret_cast<uint32_t*>(Ccp + (size_t)row * ldc + col) = cw;
                }
            }
        }
    }
}

// ---------------- kernels ----------------------------------------------------
template <int OUT_MODE>
__global__ __launch_bounds__(256) void k_gemm_proj(
    const f16* Ah, const f16* Ac, const f16* Bh, const f16* Bc,
    const float* bias, float* Cf, f16* Chp, f16* Ccp)
{
    gemm_core<OUT_MODE>(Ah, Ac, blockIdx.y * 128, 0, E_DIM,
                        Bh, Bc, blockIdx.x * 128, E_DIM, E_DIM,
                        1.0f, bias, Cf, Chp, Ccp,
                        blockIdx.y * 128, 0, E_DIM);
}

__global__ __launch_bounds__(256) void k_gemm_attn()
{
    const int h = blockIdx.z;
    const int row0 = blockIdx.y * 128;
    const int b = row0 >> 12;
    const int bh = (b << 4) + h;
    gemm_core<1>(g_Qh, g_Qc, row0, h * 128, E_DIM,
                 g_KVth + ((size_t)bh << 14), g_KVtc + ((size_t)bh << 14), 0, D_DIM, D_DIM,
                 0.08838834764831845f, nullptr, nullptr, g_ATh, g_ATc,
                 row0, h * 128, E_DIM);
}

// fp32 -> fp16 (h, c) split
__global__ __launch_bounds__(256) void k_split(const float* __restrict__ in,
                                               f16* __restrict__ hp, f16* __restrict__ cp, int n)
{
    int i = (blockIdx.x * 256 + threadIdx.x) * 4;
    if (i >= n) return;
    float4 v = *reinterpret_cast<const float4*>(in + i);
    float vv[4] = {v.x, v.y, v.z, v.w};
    uint32_t hw[2], cw[2];
    #pragma unroll
    for (int q = 0; q < 2; q++) {
        f16 h0, c0, h1, c1;
        split2(vv[q * 2 + 0], h0, c0);
        split2(vv[q * 2 + 1], h1, c1);
        hw[q] = (uint32_t)__half_as_ushort(h0) | ((uint32_t)__half_as_ushort(h1) << 16);
        cw[q] = (uint32_t)__half_as_ushort(c0) | ((uint32_t)__half_as_ushort(c1) << 16);
    }
    *reinterpret_cast<uint2*>(hp + i) = make_uint2(hw[0], hw[1]);
    *reinterpret_cast<uint2*>(cp + i) = make_uint2(cw[0], cw[1]);
}

// KVt partial: KVt[bh][e][d] = sum_{s in split} V[b,s,h,e] * K[b,s,h,d]
__global__ __launch_bounds__(256, 2) void k_kvpart()
{
    const int split = blockIdx.x;
    const int bh = blockIdx.z;
    const int b = bh >> 4;
    const int h = bh & 15;
    const float* A  = g_V + (size_t)b * T_DIM * E_DIM + h * D_DIM;
    const float* Bk = g_K + (size_t)b * T_DIM * E_DIM + h * D_DIM;
    float* Cg = g_KVp + ((size_t)(split * 64 + bh) << 14);

    __shared__ float As[16][D_DIM];
    __shared__ float Bs[16][D_DIM];

    const int tid = threadIdx.x;
    const int lr = tid >> 5;
    const int lc = (tid & 31) << 2;
    const int ty = tid >> 4;
    const int tx = tid & 15;

    float acc[8][8];
    #pragma unroll
    for (int i = 0; i < 8; i++)
        #pragma unroll
        for (int j = 0; j < 8; j++) acc[i][j] = 0.0f;

    const int s_begin = split * (T_DIM / KVSPLIT);
    const int s_end = s_begin + (T_DIM / KVSPLIT);
    for (int s0 = s_begin; s0 < s_end; s0 += 16) {
        #pragma unroll
        for (int rr = 0; rr < 2; rr++) {
            int s = lr + rr * 8;
            *reinterpret_cast<float4*>(&As[s][lc]) =
                *reinterpret_cast<const float4*>(A + (size_t)(s0 + s) * E_DIM + lc);
            *reinterpret_cast<float4*>(&Bs[s][lc]) =
                *reinterpret_cast<const float4*>(Bk + (size_t)(s0 + s) * E_DIM + lc);
        }
        __syncthreads();
        #pragma unroll
        for (int k = 0; k < 16; k++) {
            float a[8], bb[8];
            *reinterpret_cast<float4*>(a)      = *reinterpret_cast<const float4*>(&As[k][ty * 8]);
            *reinterpret_cast<float4*>(a + 4)  = *reinterpret_cast<const float4*>(&As[k][ty * 8 + 4]);
            *reinterpret_cast<float4*>(bb)     = *reinterpret_cast<const float4*>(&Bs[k][tx * 8]);
            *reinterpret_cast<float4*>(bb + 4) = *reinterpret_cast<const float4*>(&Bs[k][tx * 8 + 4]);
            #pragma unroll
            for (int i = 0; i < 8; i++)
                #pragma unroll
                for (int j = 0; j < 8; j++) acc[i][j] += a[i] * bb[j];
        }
        __syncthreads();
    }

    #pragma unroll
    for (int i = 0; i < 8; i++) {
        float* Cr = Cg + (ty * 8 + i) * D_DIM + tx * 8;
        #pragma unroll
        for (int j = 0; j < 8; j += 4)
            *reinterpret_cast<float4*>(Cr + j) = make_float4(acc[i][j], acc[i][j + 1], acc[i][j + 2], acc[i][j + 3]);
    }
}

// reduce 8 partials -> fp16 (h, c)
__global__ __launch_bounds__(256) void k_kvreduce()
{
    int idx = blockIdx.x * 256 + threadIdx.x;
    float s = 0.0f;
    #pragma unroll
    for (int p = 0; p < KVSPLIT; p++) s += g_KVp[((size_t)p << 20) + idx];
    f16 h, c;
    split2(s, h, c);
    g_KVth[idx] = h;
    g_KVtc[idx] = c;
}

// ---------------- launch -----------------------------------------------------
extern "C" void kernel_launch(void* const* d_in, const int* in_sizes, int n_in,
                              void* d_out, int out_size)
{
    const float* x  = (const float*)d_in[0];
    const float* Wq = (const float*)d_in[1];
    const float* bq = (const float*)d_in[2];
    const float* Wk = (const float*)d_in[3];
    const float* bk = (const float*)d_in[4];
    const float* Wv = (const float*)d_in[5];
    const float* bv = (const float*)d_in[6];
    const float* Wo = (const float*)d_in[7];
    const float* bo = (const float*)d_in[8];
    float* out = (float*)d_out;

    f16 *xh, *xc, *wh, *wc, *qh, *qc, *ath, *atc;
    float *Kf, *Vf;
    cudaGetSymbolAddress((void**)&xh, g_xh);
    cudaGetSymbolAddress((void**)&xc, g_xc);
    cudaGetSymbolAddress((void**)&wh, g_Wh);
    cudaGetSymbolAddress((void**)&wc, g_Wc);
    cudaGetSymbolAddress((void**)&qh, g_Qh);
    cudaGetSymbolAddress((void**)&qc, g_Qc);
    cudaGetSymbolAddress((void**)&Kf, g_K);
    cudaGetSymbolAddress((void**)&Vf, g_V);
    cudaGetSymbolAddress((void**)&ath, g_ATh);
    cudaGetSymbolAddress((void**)&atc, g_ATc);

    cudaFuncSetAttribute(k_gemm_proj<0>, cudaFuncAttributeMaxDynamicSharedMemorySize, SMEM_BYTES);
    cudaFuncSetAttribute(k_gemm_proj<1>, cudaFuncAttributeMaxDynamicSharedMemorySize, SMEM_BYTES);
    cudaFuncSetAttribute(k_gemm_attn,    cudaFuncAttributeMaxDynamicSharedMemorySize, SMEM_BYTES);

    const size_t WSZ = (size_t)E_DIM * E_DIM;
    const int NX = BT_DIM * E_DIM;

    k_split<<<NX / 1024, 256>>>(x, xh, xc, NX);
    k_split<<<(int)(WSZ / 1024), 256>>>(Wq, wh + 0 * WSZ, wc + 0 * WSZ, (int)WSZ);
    k_split<<<(int)(WSZ / 1024), 256>>>(Wk, wh + 1 * WSZ, wc + 1 * WSZ, (int)WSZ);
    k_split<<<(int)(WSZ / 1024), 256>>>(Wv, wh + 2 * WSZ, wc + 2 * WSZ, (int)WSZ);
    k_split<<<(int)(WSZ / 1024), 256>>>(Wo, wh + 3 * WSZ, wc + 3 * WSZ, (int)WSZ);

    dim3 gp(E_DIM / 128, BT_DIM / 128);  // (16, 128)

    k_gemm_proj<1><<<gp, 256, SMEM_BYTES>>>(xh, xc, wh + 0 * WSZ, wc + 0 * WSZ, bq, nullptr, qh, qc);
    k_gemm_proj<0><<<gp, 256, SMEM_BYTES>>>(xh, xc, wh + 1 * WSZ, wc + 1 * WSZ, bk, Kf, nullptr, nullptr);
    k_gemm_proj<0><<<gp, 256, SMEM_BYTES>>>(xh, xc, wh + 2 * WSZ, wc + 2 * WSZ, bv, Vf, nullptr, nullptr);

    k_kvpart<<<dim3(KVSPLIT, 1, 64), 256>>>();
    k_kvreduce<<<(64 * D_DIM * D_DIM) / 256, 256>>>();

    k_gemm_attn<<<dim3(1, BT_DIM / 128, H_DIM), 256, SMEM_BYTES>>>();

    k_gemm_proj<0><<<gp, 256, SMEM_BYTES>>>(ath, atc, wh + 3 * WSZ, wc + 3 * WSZ, bo, out, nullptr, nullptr);
}